// round 11
// baseline (speedup 1.0000x reference)
#include <cuda_runtime.h>

constexpr int Lc = 2048;
constexpr int Ic = 32000;
constexpr int Dc = 256;
constexpr int NB = 148;             // kA grid
constexpr int NT = 1024;
constexpr int NCHUNK_A = Ic / 32;   // 1000 chunks of 32 DE rows
constexpr int KO_NB = Ic / 256;     // 125 output chunks of 256 cols (single wave)

// Scratch (device globals; allocation is forbidden)
__device__ float g_part[2][NB][Dc];
__device__ float g_w[Dc];
__device__ unsigned g_count = 0;    // last-block ticket; winner self-resets

// ====== kA: dual GEMV p_k = x[L-2+k] @ DE, chain fused into last block ======
// GEMV thread (rg, cg): rg = t>>6 owns 2 rows/chunk, cg = t&63 owns 4 cols.
// Warp = 32 consecutive cg -> 512B coalesced float4 DE loads; x loads are
// warp-uniform scalars (1 request, broadcast). No smem in the hot loop.
__global__ void __launch_bounds__(NT) kA_posembed_chain(
    const float* __restrict__ x,   const float* __restrict__ DE,
    const float* __restrict__ PE,  const float* __restrict__ D1w,
    const float* __restrict__ Attw)
{
    __shared__ float sh[9216];          // GEMV reduce (8192) then chain (9216)
    __shared__ unsigned s_winner;
    const int t = threadIdx.x, b = blockIdx.x;
    const int rg = t >> 6, cg = t & 63;

    // ---------------- GEMV over this block's DE chunks ----------------
    {
        const float* xr0 = x + (size_t)(Lc - 2) * Ic;
        const float* xr1 = x + (size_t)(Lc - 1) * Ic;
        float4 a0 = make_float4(0.f, 0.f, 0.f, 0.f);
        float4 a1 = make_float4(0.f, 0.f, 0.f, 0.f);

        for (int c = b; c < NCHUNK_A; c += NB) {
            const int r = c * 32 + rg * 2;
            const float x00 = __ldg(xr0 + r), x01 = __ldg(xr0 + r + 1);
            const float x10 = __ldg(xr1 + r), x11 = __ldg(xr1 + r + 1);
            const float4 v0 = *(const float4*)(DE + (size_t)r       * Dc + cg * 4);
            const float4 v1 = *(const float4*)(DE + (size_t)(r + 1) * Dc + cg * 4);
            a0.x = fmaf(x00, v0.x, a0.x); a0.y = fmaf(x00, v0.y, a0.y);
            a0.z = fmaf(x00, v0.z, a0.z); a0.w = fmaf(x00, v0.w, a0.w);
            a0.x = fmaf(x01, v1.x, a0.x); a0.y = fmaf(x01, v1.y, a0.y);
            a0.z = fmaf(x01, v1.z, a0.z); a0.w = fmaf(x01, v1.w, a0.w);
            a1.x = fmaf(x10, v0.x, a1.x); a1.y = fmaf(x10, v0.y, a1.y);
            a1.z = fmaf(x10, v0.z, a1.z); a1.w = fmaf(x10, v0.w, a1.w);
            a1.x = fmaf(x11, v1.x, a1.x); a1.y = fmaf(x11, v1.y, a1.y);
            a1.z = fmaf(x11, v1.z, a1.z); a1.w = fmaf(x11, v1.w, a1.w);
        }

        float* red0 = sh;             // [16][256]
        float* red1 = sh + 4096;      // [16][256]
        *(float4*)(red0 + rg * 256 + cg * 4) = a0;
        *(float4*)(red1 + rg * 256 + cg * 4) = a1;
        __syncthreads();
        if (t < 256) {
            float s0 = 0.f, s1 = 0.f;
            #pragma unroll
            for (int j = 0; j < 16; ++j) {
                s0 += red0[j * 256 + t];
                s1 += red1[j * 256 + t];
            }
            g_part[0][b][t] = s0;
            g_part[1][b][t] = s1;
        }
    }

    // Warm D1 + Att (+PE rows) into L2 for the chain tail
    {
        const int idx = b * NT + t;
        if (idx < (2 * Dc * Dc) / 4) {
            float4 v = __ldcg((const float4*)D1w  + idx);
            float4 u = __ldcg((const float4*)Attw + idx);
            float s = v.x + v.y + v.z + v.w + u.x + u.y + u.z + u.w;
            asm volatile("" :: "f"(s));
        }
        if (b == 1 && t < 128) {
            float4 v = __ldcg((const float4*)(PE + (size_t)(Lc - 2) * Dc) + t);
            asm volatile("" :: "f"(v.x + v.y + v.z + v.w));
        }
    }

    // ---------------- last-block ticket ----------------
    __syncthreads();                    // g_part writes done block-wide
    if (t == 0) {
        __threadfence();                // publish g_part
        unsigned old = atomicAdd(&g_count, 1u);
        s_winner = (old == (unsigned)(NB - 1));
        if (s_winner) {
            g_count = 0;                // self-reset for next graph replay
            __threadfence();            // acquire: all g_part visible below
        }
    }
    __syncthreads();
    if (!s_winner) return;

    // ---------------- chain (winner block only, inputs L2-hot) ----------------
    const float inv1 = 1.0f / (float)(Lc - 1);
    const float inv2 = 1.0f / (float)Lc;
    float* sc0 = sh;                    // 512
    float* sc1 = sh + 512;              // 512
    float* sp0 = sh + 1024;             // [16][256]
    float* sp1 = sh + 5120;             // [16][256]
    const int col = t & 255, q = t >> 8;

    // p-reduce over 148 block-partials (4-way split) + PE bias
    {
        float r0s = 0.f, r1s = 0.f;
        #pragma unroll 4
        for (int i = q; i < NB; i += 4) {
            r0s += g_part[0][i][col];
            r1s += g_part[1][i][col];
        }
        sp0[q * 256 + col] = r0s;
        sp1[q * 256 + col] = r1s;
        __syncthreads();
        if (t < 256) {
            float p0 = PE[(size_t)(Lc - 2) * Dc + t]
                     + sp0[t] + sp0[256 + t] + sp0[512 + t] + sp0[768 + t];
            float p1 = PE[(size_t)(Lc - 1) * Dc + t]
                     + sp1[t] + sp1[256 + t] + sp1[512 + t] + sp1[768 + t];
            sc0[t] = p0;  sc0[Dc + t] = (p0 + p1) * inv1;   // pool1 rows
            sc1[t] = p1;  sc1[Dc + t] = p1 * inv2;
        }
        __syncthreads();
    }

    const int kk = t >> 6;      // 16-way k-split over the 512 concat dim
    const int cgc = t & 63;     // 4 columns each
    float d0f = 0.f, d1f = 0.f;

    // dense1 = concat(p, pool1) @ D1
    {
        float d00=0,d01=0,d02=0,d03=0, d10=0,d11=0,d12=0,d13=0;
        #pragma unroll 8
        for (int k = kk; k < 2 * Dc; k += 16) {
            float4 v = *(const float4*)(D1w + (size_t)k * Dc + cgc * 4);
            float c0 = sc0[k], c1 = sc1[k];
            d00 = fmaf(c0, v.x, d00); d01 = fmaf(c0, v.y, d01);
            d02 = fmaf(c0, v.z, d02); d03 = fmaf(c0, v.w, d03);
            d10 = fmaf(c1, v.x, d10); d11 = fmaf(c1, v.y, d11);
            d12 = fmaf(c1, v.z, d12); d13 = fmaf(c1, v.w, d13);
        }
        const int o = kk * 256 + cgc * 4;
        sp0[o+0]=d00; sp0[o+1]=d01; sp0[o+2]=d02; sp0[o+3]=d03;
        sp1[o+0]=d10; sp1[o+1]=d11; sp1[o+2]=d12; sp1[o+3]=d13;
        __syncthreads();
        if (t < 256) {
            #pragma unroll
            for (int j = 0; j < 16; ++j) { d0f += sp0[j*256+t]; d1f += sp1[j*256+t]; }
            sc0[t] = d0f;  sc0[Dc + t] = (d0f + d1f) * inv1;  // pool2 rows
            sc1[t] = d1f;  sc1[Dc + t] = d1f * inv2;
        }
        __syncthreads();
    }

    // attention = concat(dense1, pool2) @ Att;  w = d0*a0 + d1*a1
    {
        float a00=0,a01=0,a02=0,a03=0, a10=0,a11=0,a12=0,a13=0;
        #pragma unroll 8
        for (int k = kk; k < 2 * Dc; k += 16) {
            float4 v = *(const float4*)(Attw + (size_t)k * Dc + cgc * 4);
            float c0 = sc0[k], c1 = sc1[k];
            a00 = fmaf(c0, v.x, a00); a01 = fmaf(c0, v.y, a01);
            a02 = fmaf(c0, v.z, a02); a03 = fmaf(c0, v.w, a03);
            a10 = fmaf(c1, v.x, a10); a11 = fmaf(c1, v.y, a11);
            a12 = fmaf(c1, v.z, a12); a13 = fmaf(c1, v.w, a13);
        }
        const int o = kk * 256 + cgc * 4;
        sp0[o+0]=a00; sp0[o+1]=a01; sp0[o+2]=a02; sp0[o+3]=a03;
        sp1[o+0]=a10; sp1[o+1]=a11; sp1[o+2]=a12; sp1[o+3]=a13;
        __syncthreads();
        if (t < 256) {
            float a0f = 0.f, a1f = 0.f;
            #pragma unroll
            for (int j = 0; j < 16; ++j) { a0f += sp0[j*256+t]; a1f += sp1[j*256+t]; }
            g_w[t] = d0f * a0f + d1f * a1f;   // SA.T sum of the 2 surviving rows
        }
    }
}

// ============ kOut: out[i] = sum_d w[d] * D2[d][i], one HBM pass ============
// 125 blocks x 1024 threads, single wave. Thread = (dg 0..15, colg 0..63):
// 16 independent coalesced float4 loads per thread -> high MLP, shared reduce.
__global__ void __launch_bounds__(NT) kOut(
    const float* __restrict__ D2w, float* __restrict__ out)
{
    __shared__ float sw[Dc];
    __shared__ float red[16 * 256];
    const int t = threadIdx.x, b = blockIdx.x;
    const int colg = t & 63;   // 4 output cols
    const int dg   = t >> 6;   // 16 d's

    if (t < Dc) sw[t] = g_w[t];
    __syncthreads();

    const float* base = D2w + (size_t)(dg * 16) * Ic + b * 256 + colg * 4;
    const float* swq  = sw + dg * 16;
    float4 acc = make_float4(0.f, 0.f, 0.f, 0.f);
    #pragma unroll
    for (int d = 0; d < 16; ++d) {
        const float4 v = *(const float4*)(base + (size_t)d * Ic);
        const float wv = swq[d];
        acc.x = fmaf(wv, v.x, acc.x); acc.y = fmaf(wv, v.y, acc.y);
        acc.z = fmaf(wv, v.z, acc.z); acc.w = fmaf(wv, v.w, acc.w);
    }
    *(float4*)(red + dg * 256 + colg * 4) = acc;
    __syncthreads();
    if (t < 256) {
        float s = 0.f;
        #pragma unroll
        for (int j = 0; j < 16; ++j) s += red[j * 256 + t];
        out[b * 256 + t] = s;
    }
}

extern "C" void kernel_launch(void* const* d_in, const int* in_sizes, int n_in,
                              void* d_out, int out_size) {
    const float* x   = (const float*)d_in[0];  // [L, I]
    const float* DE  = (const float*)d_in[1];  // [I, D]
    const float* PE  = (const float*)d_in[2];  // [L, D]
    const float* D1w = (const float*)d_in[3];  // [2D, D]
    const float* D2w = (const float*)d_in[4];  // [D, I]
    const float* Att = (const float*)d_in[5];  // [2D, D]
    float* out = (float*)d_out;                // [1, I]
    (void)in_sizes; (void)n_in; (void)out_size;

    kA_posembed_chain<<<NB, NT>>>(x, DE, PE, D1w, Att);
    kOut<<<KO_NB, NT>>>(D2w, out);
}